// round 13
// baseline (speedup 1.0000x reference)
#include <cuda_runtime.h>
#include <math.h>

#define NN 50000
#define MAXE 1000000   // E (800000) + self loops (50000), with margin

// ---------------- device scratch ----------------
__device__ float g_xl1[NN * 256];   // x @ W1          [N,4,64]
__device__ float g_h  [NN * 256];   // layer-1 output (post ELU)
__device__ float g_xl2[NN * 64];    // h @ W2          [N,1,64]
__device__ float g_as1[NN * 4];
__device__ float g_ad1[NN * 4];
__device__ float g_as2[NN];
__device__ float g_ad2[NN];
__device__ int   g_deg[NN];
__device__ int   g_rowptr[NN + 1];
__device__ int   g_cursor[NN];
__device__ int   g_csr[MAXE];
__device__ int   g_is64;

__device__ __forceinline__ int edge_at(const void* ei, long long i, int is64) {
    return is64 ? (int)((const long long*)ei)[i] : ((const int*)ei)[i];
}

__global__ void k_init() {
    int i = blockIdx.x * blockDim.x + threadIdx.x;
    if (i < NN) g_deg[i] = 0;
    if (i == 0) g_is64 = 1;
}

__global__ void k_detect(const void* ei, int n_slots) {
    int t = threadIdx.x;
    const long long* p = (const long long*)ei;
    for (int j = t; j < n_slots; j += blockDim.x) {
        long long v = p[j];
        if (v < 0 || v >= NN) { atomicExch(&g_is64, 0); break; }
    }
}

// ---------------- tiled SGEMM + fused per-row attention-logit epilogue ----------------
// C[M,N] = A[M,K] @ B[K,N]; 64x64 tile, BK=16, 256 threads, 4x4 micro tile.
// N-tile (64 cols) == one attention head. Epilogue computes the partial dot of
// each row's 64 cols with asv/adv and stores (single writer per (row, head)):
//   as_out[row*hstride + blockIdx.y], ad_out[...].
__global__ void __launch_bounds__(256) k_gemm(
        const float* __restrict__ A, const float* __restrict__ B,
        float* __restrict__ C, int M, int N, int K,
        const float* __restrict__ asv, const float* __restrict__ adv,
        float* __restrict__ as_out, float* __restrict__ ad_out, int hstride) {
    __shared__ float As[16][68];   // As[k][m]
    __shared__ float Bs[16][68];   // Bs[k][n]
    int t  = threadIdx.x;
    int tx = t & 15, ty = t >> 4;
    int bm0 = blockIdx.x * 64, bn0 = blockIdx.y * 64;

    int ar  = t >> 2, ac4 = (t & 3) * 4;    // A tile load coords
    int br  = t >> 4, bc4 = (t & 15) * 4;   // B tile load coords
    int grow = bm0 + ar;

    float acc[4][4] = {};

    // stage 0 prefetch
    float4 av = make_float4(0.f, 0.f, 0.f, 0.f);
    if (grow < M) av = *(const float4*)(A + (size_t)grow * K + ac4);
    float4 bv = *(const float4*)(B + (size_t)br * N + bn0 + bc4);

    for (int kt = 0; kt < K; kt += 16) {
        As[ac4 + 0][ar] = av.x; As[ac4 + 1][ar] = av.y;
        As[ac4 + 2][ar] = av.z; As[ac4 + 3][ar] = av.w;
        *(float4*)&Bs[br][bc4] = bv;
        __syncthreads();

        // prefetch next K-tile into registers while computing from smem
        if (kt + 16 < K) {
            if (grow < M) av = *(const float4*)(A + (size_t)grow * K + kt + 16 + ac4);
            bv = *(const float4*)(B + (size_t)(kt + 16 + br) * N + bn0 + bc4);
        }

        #pragma unroll
        for (int k = 0; k < 16; k++) {
            float4 a = *(float4*)&As[k][ty * 4];
            float4 b = *(float4*)&Bs[k][tx * 4];
            acc[0][0] += a.x * b.x; acc[0][1] += a.x * b.y; acc[0][2] += a.x * b.z; acc[0][3] += a.x * b.w;
            acc[1][0] += a.y * b.x; acc[1][1] += a.y * b.y; acc[1][2] += a.y * b.z; acc[1][3] += a.y * b.w;
            acc[2][0] += a.z * b.x; acc[2][1] += a.z * b.y; acc[2][2] += a.z * b.z; acc[2][3] += a.z * b.w;
            acc[3][0] += a.w * b.x; acc[3][1] += a.w * b.y; acc[3][2] += a.w * b.z; acc[3][3] += a.w * b.w;
        }
        __syncthreads();
    }

    #pragma unroll
    for (int i = 0; i < 4; i++) {
        int row = bm0 + ty * 4 + i;
        if (row < M) {
            float4 o = make_float4(acc[i][0], acc[i][1], acc[i][2], acc[i][3]);
            *(float4*)(C + (size_t)row * N + bn0 + tx * 4) = o;
        }
    }

    // ---- fused attention-logit epilogue ----
    const float4 a4 = *(const float4*)(asv + bn0 + tx * 4);
    const float4 d4 = *(const float4*)(adv + bn0 + tx * 4);
    float ps[4], pd[4];
    #pragma unroll
    for (int i = 0; i < 4; i++) {
        ps[i] = acc[i][0] * a4.x + acc[i][1] * a4.y + acc[i][2] * a4.z + acc[i][3] * a4.w;
        pd[i] = acc[i][0] * d4.x + acc[i][1] * d4.y + acc[i][2] * d4.z + acc[i][3] * d4.w;
    }
    // reduce across the 16 tx lanes (lanes 0-15 and 16-31 are independent ty's)
    #pragma unroll
    for (int off = 8; off; off >>= 1) {
        #pragma unroll
        for (int i = 0; i < 4; i++) {
            ps[i] += __shfl_xor_sync(0xFFFFFFFFu, ps[i], off);
            pd[i] += __shfl_xor_sync(0xFFFFFFFFu, pd[i], off);
        }
    }
    if (tx == 0) {
        #pragma unroll
        for (int i = 0; i < 4; i++) {
            int row = bm0 + ty * 4 + i;
            if (row < M) {
                as_out[row * hstride + blockIdx.y] = ps[i];
                ad_out[row * hstride + blockIdx.y] = pd[i];
            }
        }
    }
}

// ---------------- CSR build ----------------
__global__ void k_hist(const void* ei, int E) {
    int i = blockIdx.x * blockDim.x + threadIdx.x;
    int Et = E + NN;
    if (i >= Et) return;
    int is64 = g_is64;
    int d = (i < E) ? edge_at(ei, (long long)E + i, is64) : (i - E);
    atomicAdd(&g_deg[d], 1);
}

__global__ void k_scan() {   // single block, 1024 threads
    __shared__ int sums[1024];
    int t = threadIdx.x;
    const int chunk = (NN + 1023) / 1024;
    int lo = t * chunk;
    int hi = lo + chunk; if (hi > NN) hi = NN; if (lo > NN) lo = NN;
    int s = 0;
    for (int i = lo; i < hi; i++) s += g_deg[i];
    sums[t] = s;
    __syncthreads();
    for (int off = 1; off < 1024; off <<= 1) {
        int v = (t >= off) ? sums[t - off] : 0;
        __syncthreads();
        sums[t] += v;
        __syncthreads();
    }
    int run = sums[t] - s;   // exclusive prefix
    for (int i = lo; i < hi; i++) {
        g_rowptr[i] = run;
        g_cursor[i] = run;
        run += g_deg[i];
    }
    if (t == 1023) g_rowptr[NN] = sums[1023];
}

__global__ void k_scatter(const void* ei, int E) {
    int i = blockIdx.x * blockDim.x + threadIdx.x;
    int Et = E + NN;
    if (i >= Et) return;
    int is64 = g_is64;
    int s, d;
    if (i < E) {
        s = edge_at(ei, i, is64);
        d = edge_at(ei, (long long)E + i, is64);
    } else {
        s = d = i - E;
    }
    int pos = atomicAdd(&g_cursor[d], 1);
    g_csr[pos] = s;
}

// ---------------- layer-1 aggregation: warp per dst, float4 gathers ----------------
// Lane L owns cols [L*4, L*4+3] (j=0, heads 0/1) and [128+L*4, 128+L*4+3] (j=1, heads 2/3).
__global__ void __launch_bounds__(256) k_agg1(const float* __restrict__ b1) {
    int d = (blockIdx.x * blockDim.x + threadIdx.x) >> 5;
    int lane = threadIdx.x & 31;
    if (d >= NN) return;
    int beg = g_rowptr[d], end = g_rowptr[d + 1];
    bool lo16 = lane < 16;

    const float4 adv = *(const float4*)(g_ad1 + d * 4);
    float m0 = -1e30f, m1 = -1e30f, m2 = -1e30f, m3 = -1e30f;
    float s0 = 0.f, s1 = 0.f, s2 = 0.f, s3 = 0.f;
    float4 accA = make_float4(0.f, 0.f, 0.f, 0.f);
    float4 accB = make_float4(0.f, 0.f, 0.f, 0.f);

    int src_next = (beg < end) ? g_csr[beg] : 0;
    for (int k = beg; k < end; k++) {
        int src = src_next;
        if (k + 1 < end) src_next = g_csr[k + 1];   // prefetch next index
        const float4* xr4 = (const float4*)(g_xl1 + (size_t)src * 256);
        const float4 asv = *(const float4*)(g_as1 + src * 4);

        float e0 = asv.x + adv.x, e1 = asv.y + adv.y, e2 = asv.z + adv.z, e3 = asv.w + adv.w;
        e0 = e0 > 0.f ? e0 : 0.2f * e0;
        e1 = e1 > 0.f ? e1 : 0.2f * e1;
        e2 = e2 > 0.f ? e2 : 0.2f * e2;
        e3 = e3 > 0.f ? e3 : 0.2f * e3;

        float p0, p1, p2, p3, c0, c1, c2, c3;
        if (e0 > m0) { c0 = __expf(m0 - e0); p0 = 1.f; m0 = e0; } else { c0 = 1.f; p0 = __expf(e0 - m0); }
        if (e1 > m1) { c1 = __expf(m1 - e1); p1 = 1.f; m1 = e1; } else { c1 = 1.f; p1 = __expf(e1 - m1); }
        if (e2 > m2) { c2 = __expf(m2 - e2); p2 = 1.f; m2 = e2; } else { c2 = 1.f; p2 = __expf(e2 - m2); }
        if (e3 > m3) { c3 = __expf(m3 - e3); p3 = 1.f; m3 = e3; } else { c3 = 1.f; p3 = __expf(e3 - m3); }
        s0 = s0 * c0 + p0; s1 = s1 * c1 + p1; s2 = s2 * c2 + p2; s3 = s3 * c3 + p3;

        float scA = lo16 ? c0 : c1, pA = lo16 ? p0 : p1;
        float scB = lo16 ? c2 : c3, pB = lo16 ? p2 : p3;

        float4 vA = xr4[lane];
        float4 vB = xr4[32 + lane];
        accA.x = accA.x * scA + pA * vA.x; accA.y = accA.y * scA + pA * vA.y;
        accA.z = accA.z * scA + pA * vA.z; accA.w = accA.w * scA + pA * vA.w;
        accB.x = accB.x * scB + pB * vB.x; accB.y = accB.y * scB + pB * vB.y;
        accB.z = accB.z * scB + pB * vB.z; accB.w = accB.w * scB + pB * vB.w;
    }

    float sA = lo16 ? s0 : s1;
    float sB = lo16 ? s2 : s3;
    float rA = 1.f / sA, rB = 1.f / sB;
    const float4 bA = *(const float4*)(b1 + lane * 4);
    const float4 bB = *(const float4*)(b1 + 128 + lane * 4);

    float4 oA, oB;
    oA.x = accA.x * rA + bA.x; oA.y = accA.y * rA + bA.y;
    oA.z = accA.z * rA + bA.z; oA.w = accA.w * rA + bA.w;
    oB.x = accB.x * rB + bB.x; oB.y = accB.y * rB + bB.y;
    oB.z = accB.z * rB + bB.z; oB.w = accB.w * rB + bB.w;
    oA.x = oA.x > 0.f ? oA.x : (__expf(oA.x) - 1.f);
    oA.y = oA.y > 0.f ? oA.y : (__expf(oA.y) - 1.f);
    oA.z = oA.z > 0.f ? oA.z : (__expf(oA.z) - 1.f);
    oA.w = oA.w > 0.f ? oA.w : (__expf(oA.w) - 1.f);
    oB.x = oB.x > 0.f ? oB.x : (__expf(oB.x) - 1.f);
    oB.y = oB.y > 0.f ? oB.y : (__expf(oB.y) - 1.f);
    oB.z = oB.z > 0.f ? oB.z : (__expf(oB.z) - 1.f);
    oB.w = oB.w > 0.f ? oB.w : (__expf(oB.w) - 1.f);

    *(float4*)(g_h + (size_t)d * 256 + lane * 4)       = oA;
    *(float4*)(g_h + (size_t)d * 256 + 128 + lane * 4) = oB;
}

// ---------------- layer-2 aggregation: warp per dst, float2 gathers ----------------
__global__ void __launch_bounds__(256) k_agg2(
        const float* __restrict__ b2, float* __restrict__ out) {
    int d = (blockIdx.x * blockDim.x + threadIdx.x) >> 5;
    int lane = threadIdx.x & 31;
    if (d >= NN) return;
    int beg = g_rowptr[d], end = g_rowptr[d + 1];
    float ad = g_ad2[d];
    float m = -1e30f, s = 0.f;
    float a0 = 0.f, a1 = 0.f;

    int src_next = (beg < end) ? g_csr[beg] : 0;
    for (int k = beg; k < end; k++) {
        int src = src_next;
        if (k + 1 < end) src_next = g_csr[k + 1];
        float e = g_as2[src] + ad;
        e = e > 0.f ? e : 0.2f * e;
        float p, sc;
        if (e > m) { sc = __expf(m - e); p = 1.f; m = e; }
        else       { sc = 1.f; p = __expf(e - m); }
        s = s * sc + p;
        const float2 v = *(const float2*)(g_xl2 + (size_t)src * 64 + lane * 2);
        a0 = a0 * sc + p * v.x;
        a1 = a1 * sc + p * v.y;
    }
    float r = 1.f / s;
    const float2 b = *(const float2*)(b2 + lane * 2);
    float2 o;
    o.x = a0 * r + b.x;
    o.y = a1 * r + b.y;
    *(float2*)(out + (size_t)d * 64 + lane * 2) = o;
}

// ---------------- launch ----------------
extern "C" void kernel_launch(void* const* d_in, const int* in_sizes, int n_in,
                              void* d_out, int out_size) {
    const float* x    = (const float*)d_in[0];
    const void*  ei   = d_in[1];
    const float* W1   = (const float*)d_in[2];
    const float* as1v = (const float*)d_in[3];
    const float* ad1v = (const float*)d_in[4];
    const float* b1   = (const float*)d_in[5];
    const float* W2   = (const float*)d_in[6];
    const float* as2v = (const float*)d_in[7];
    const float* ad2v = (const float*)d_in[8];
    const float* b2   = (const float*)d_in[9];

    int E  = in_sizes[1] / 2;
    int Et = E + NN;

    float *p_xl1, *p_h, *p_xl2, *p_as1, *p_ad1, *p_as2, *p_ad2;
    cudaGetSymbolAddress((void**)&p_xl1, g_xl1);
    cudaGetSymbolAddress((void**)&p_h,   g_h);
    cudaGetSymbolAddress((void**)&p_xl2, g_xl2);
    cudaGetSymbolAddress((void**)&p_as1, g_as1);
    cudaGetSymbolAddress((void**)&p_ad1, g_ad1);
    cudaGetSymbolAddress((void**)&p_as2, g_as2);
    cudaGetSymbolAddress((void**)&p_ad2, g_ad2);

    k_init<<<(NN + 255) / 256, 256>>>();
    int slots = E < 1024 ? E : 1024;
    k_detect<<<1, 256>>>(ei, slots);

    dim3 g1((NN + 63) / 64, 256 / 64);
    k_gemm<<<g1, 256>>>(x, W1, p_xl1, NN, 256, 128, as1v, ad1v, p_as1, p_ad1, 4);

    k_hist<<<(Et + 255) / 256, 256>>>(ei, E);
    k_scan<<<1, 1024>>>();
    k_scatter<<<(Et + 255) / 256, 256>>>(ei, E);

    k_agg1<<<(NN * 32 + 255) / 256, 256>>>(b1);

    dim3 g2((NN + 63) / 64, 1);
    k_gemm<<<g2, 256>>>(p_h, W2, p_xl2, NN, 64, 256, as2v, ad2v, p_as2, p_ad2, 1);

    k_agg2<<<(NN * 32 + 255) / 256, 256>>>(b2, (float*)d_out);
}